// round 1
// baseline (speedup 1.0000x reference)
#include <cuda_runtime.h>
#include <cuda_bf16.h>
#include <math.h>

// ---------------- problem constants ----------------
#define BATCH 2048
#define LD    100
#define DIM   128
#define CONV  128
#define CC    512          // C = CONV*4
#define L1O   97           // 100-4+1
#define L2O   92           // 97-6+1
#define L3O   85           // 92-8+1

// ---------------- scratch (device globals; allocation-free) ----------------
__device__ float g_x  [BATCH * LD  * DIM];     // embedded drug (B,L,128)
__device__ float g_h1 [BATCH * L1O * 128];
__device__ float g_h2 [BATCH * L2O * 256];
__device__ float g_dc [BATCH * L3O * 512];     // drugConv (B,85,512)
__device__ float g_att[BATCH * L3O * 512];     // drug_att -> s (in place)
__device__ float g_Am [BATCH * L3O * 512];     // A
__device__ float g_w1r[128 * 512];
__device__ float g_w2r[256 * 768];
__device__ float g_w3r[512 * 2048];
__device__ float g_fwm1[128 * 7];
__device__ float g_fwm2[256 * 128];
__device__ float g_fwm3[512 * 256];
__device__ float g_hf1[BATCH * 128];
__device__ float g_hf2[BATCH * 256];
__device__ float g_fnn[BATCH * 512];
__device__ float g_fatt[BATCH * 512];
__device__ float g_pair[BATCH * 1024];
__device__ float g_fh1[BATCH * 1024];
__device__ float g_fh2[BATCH * 1024];
__device__ float g_fh3[BATCH * 512];

// ---------------- small prep kernels ----------------
__global__ void embed_k(const int* __restrict__ drug, const float* __restrict__ emb,
                        float* __restrict__ x) {
    int idx = blockIdx.x * blockDim.x + threadIdx.x;   // one float4 each
    const int total = BATCH * LD * (DIM / 4);
    if (idx >= total) return;
    int d4 = idx & 31;
    int bl = idx >> 5;
    int tok = drug[bl];
    ((float4*)x)[(size_t)bl * 32 + d4] = ((const float4*)emb)[(size_t)tok * 32 + d4];
}

// w[o][i][k] -> wr[o][k*Ci+i]
__global__ void reorder_w(const float* __restrict__ w, float* __restrict__ wr,
                          int O, int Ci, int Kw) {
    int idx = blockIdx.x * blockDim.x + threadIdx.x;
    int total = O * Ci * Kw;
    if (idx >= total) return;
    int o = idx / (Ci * Kw);
    int r = idx - o * (Ci * Kw);
    int i = r / Kw;
    int k = r - i * Kw;
    wr[(size_t)o * Ci * Kw + k * Ci + i] = w[idx];
}

// middle tap of 3-wide conv: wr[o*Ci+i] = w[(o*Ci+i)*3 + 1]
__global__ void midtap_k(const float* __restrict__ w, float* __restrict__ wr, int total) {
    int idx = blockIdx.x * blockDim.x + threadIdx.x;
    if (idx >= total) return;
    wr[idx] = w[idx * 3 + 1];
}

// feature layer 1 : out[b,o] = relu(sum_{i<7} feat[b,i]*wm[o,i] + b[o])
__global__ void feat1_k(const float* __restrict__ feat, const float* __restrict__ wm,
                        const float* __restrict__ bias, float* __restrict__ out) {
    int idx = blockIdx.x * blockDim.x + threadIdx.x;   // BATCH*128
    if (idx >= BATCH * 128) return;
    int b = idx >> 7, o = idx & 127;
    float s = bias[o];
#pragma unroll
    for (int i = 0; i < 7; i++) s = fmaf(feat[b * 7 + i], wm[o * 7 + i], s);
    out[idx] = fmaxf(s, 0.f);
}

// s = relu(drug_att + feature_att broadcast), in place on att
__global__ void s_relu_k(float* __restrict__ att, const float* __restrict__ fatt) {
    long idx = (long)blockIdx.x * blockDim.x + threadIdx.x;
    const long total = (long)BATCH * L3O * 512;
    if (idx >= total) return;
    int c = (int)(idx & 511);
    int b = (int)(idx / (L3O * 512));
    float v = att[idx] + fatt[b * 512 + c];
    att[idx] = v > 0.f ? v : 0.f;
}

// per (b,c): vd = max_l dc*(0.5+sig(A)); vf = fnn*(0.5+sig(mean_l A)); write pair
__global__ void reduce_k(const float* __restrict__ dc, const float* __restrict__ Am,
                         const float* __restrict__ fnn, float* __restrict__ pair) {
    int b = blockIdx.x;
    int c = threadIdx.x;   // 512
    const float* dp = dc + (size_t)b * L3O * 512 + c;
    const float* ap = Am + (size_t)b * L3O * 512 + c;
    float mx = -1e30f, sm = 0.f;
#pragma unroll 5
    for (int l = 0; l < L3O; l++) {
        float a = ap[(size_t)l * 512];
        float d = dp[(size_t)l * 512];
        float sg = 1.f / (1.f + expf(-a));
        mx = fmaxf(mx, d * (0.5f + sg));
        sm += a;
    }
    float fsig = 1.f / (1.f + expf(-sm * (1.0f / L3O)));
    pair[(size_t)b * 1024 + c]       = mx;
    pair[(size_t)b * 1024 + 512 + c] = fnn[(size_t)b * 512 + c] * (0.5f + fsig);
}

__global__ void final_k(const float* __restrict__ h3, const float* __restrict__ Wo,
                        const float* __restrict__ bo, float* __restrict__ out) {
    int b = blockIdx.x;
    int t = threadIdx.x;   // 128
    float s = 0.f;
#pragma unroll
    for (int c = t; c < 512; c += 128) s = fmaf(h3[(size_t)b * 512 + c], Wo[c], s);
#pragma unroll
    for (int o = 16; o > 0; o >>= 1) s += __shfl_down_sync(0xffffffffu, s, o);
    __shared__ float red[4];
    if ((t & 31) == 0) red[t >> 5] = s;
    __syncthreads();
    if (t == 0) out[b] = red[0] + red[1] + red[2] + red[3] + bo[0];
}

// ---------------- tiled SGEMM: C = act(A * W^T + bias) ----------------
// A rows addressed as A + (m/Lout)*sOuter + (m%Lout)*sInner (conv-as-gemm or plain)
// W is (N,K) row-major. Requires: M%128==0, N%128==0, K%16==0.
#define TILE 128
#define KT   16

template <int ACT>
__global__ __launch_bounds__(256, 2)
void gemm_bt(const float* __restrict__ A, const float* __restrict__ W,
             const float* __restrict__ bias, float* __restrict__ C,
             int M, int N, int K, int Lout, long sOuter, long sInner) {
    __shared__ float As[KT][TILE + 4];
    __shared__ float Bs[KT][TILE + 4];

    const int tid = threadIdx.x;
    const int m0 = blockIdx.y * TILE;
    const int n0 = blockIdx.x * TILE;

    const int lr = tid >> 2;          // 0..63
    const int c4 = (tid & 3) * 4;     // 0,4,8,12

    int mA0 = m0 + lr, mA1 = mA0 + 64;
    const float* ap0 = A + (long)(mA0 / Lout) * sOuter + (long)(mA0 % Lout) * sInner;
    const float* ap1 = A + (long)(mA1 / Lout) * sOuter + (long)(mA1 % Lout) * sInner;
    const float* bp0 = W + (long)(n0 + lr) * K;
    const float* bp1 = W + (long)(n0 + lr + 64) * K;

    float4 ra0 = *(const float4*)(ap0 + c4);
    float4 ra1 = *(const float4*)(ap1 + c4);
    float4 rb0 = *(const float4*)(bp0 + c4);
    float4 rb1 = *(const float4*)(bp1 + c4);

    float acc[8][8];
#pragma unroll
    for (int i = 0; i < 8; i++)
#pragma unroll
        for (int j = 0; j < 8; j++) acc[i][j] = 0.f;

    const int ty8 = (tid >> 4) * 8;
    const int tx8 = (tid & 15) * 8;

    for (int k0 = 0; k0 < K; k0 += KT) {
        __syncthreads();
        As[c4 + 0][lr] = ra0.x; As[c4 + 1][lr] = ra0.y; As[c4 + 2][lr] = ra0.z; As[c4 + 3][lr] = ra0.w;
        As[c4 + 0][lr + 64] = ra1.x; As[c4 + 1][lr + 64] = ra1.y; As[c4 + 2][lr + 64] = ra1.z; As[c4 + 3][lr + 64] = ra1.w;
        Bs[c4 + 0][lr] = rb0.x; Bs[c4 + 1][lr] = rb0.y; Bs[c4 + 2][lr] = rb0.z; Bs[c4 + 3][lr] = rb0.w;
        Bs[c4 + 0][lr + 64] = rb1.x; Bs[c4 + 1][lr + 64] = rb1.y; Bs[c4 + 2][lr + 64] = rb1.z; Bs[c4 + 3][lr + 64] = rb1.w;
        __syncthreads();

        int kn = k0 + KT;
        if (kn < K) {
            ra0 = *(const float4*)(ap0 + kn + c4);
            ra1 = *(const float4*)(ap1 + kn + c4);
            rb0 = *(const float4*)(bp0 + kn + c4);
            rb1 = *(const float4*)(bp1 + kn + c4);
        }

#pragma unroll
        for (int kk = 0; kk < KT; kk++) {
            float4 a0 = *(const float4*)&As[kk][ty8];
            float4 a1 = *(const float4*)&As[kk][ty8 + 4];
            float4 b0 = *(const float4*)&Bs[kk][tx8];
            float4 b1 = *(const float4*)&Bs[kk][tx8 + 4];
            float a[8] = {a0.x, a0.y, a0.z, a0.w, a1.x, a1.y, a1.z, a1.w};
            float b[8] = {b0.x, b0.y, b0.z, b0.w, b1.x, b1.y, b1.z, b1.w};
#pragma unroll
            for (int i = 0; i < 8; i++)
#pragma unroll
                for (int j = 0; j < 8; j++)
                    acc[i][j] = fmaf(a[i], b[j], acc[i][j]);
        }
    }

#pragma unroll
    for (int i = 0; i < 8; i++) {
        long m = m0 + ty8 + i;
#pragma unroll
        for (int j = 0; j < 8; j += 4) {
            int n = n0 + tx8 + j;
            float4 v;
            v.x = acc[i][j + 0] + bias[n + 0];
            v.y = acc[i][j + 1] + bias[n + 1];
            v.z = acc[i][j + 2] + bias[n + 2];
            v.w = acc[i][j + 3] + bias[n + 3];
            if (ACT == 1) {
                v.x = fmaxf(v.x, 0.f); v.y = fmaxf(v.y, 0.f);
                v.z = fmaxf(v.z, 0.f); v.w = fmaxf(v.w, 0.f);
            } else if (ACT == 2) {
                v.x = v.x > 0.f ? v.x : 0.01f * v.x;
                v.y = v.y > 0.f ? v.y : 0.01f * v.y;
                v.z = v.z > 0.f ? v.z : 0.01f * v.z;
                v.w = v.w > 0.f ? v.w : 0.01f * v.w;
            }
            *(float4*)&C[m * N + n] = v;
        }
    }
}

// ---------------- host launch ----------------
extern "C" void kernel_launch(void* const* d_in, const int* in_sizes, int n_in,
                              void* d_out, int out_size) {
    const int*   drug    = (const int*)  d_in[0];
    const float* feature = (const float*)d_in[1];
    const float* emb     = (const float*)d_in[2];
    const float* dw1 = (const float*)d_in[3];  const float* db1 = (const float*)d_in[4];
    const float* dw2 = (const float*)d_in[5];  const float* db2 = (const float*)d_in[6];
    const float* dw3 = (const float*)d_in[7];  const float* db3 = (const float*)d_in[8];
    const float* fw1 = (const float*)d_in[9];  const float* fb1 = (const float*)d_in[10];
    const float* fw2 = (const float*)d_in[11]; const float* fb2 = (const float*)d_in[12];
    const float* fw3 = (const float*)d_in[13]; const float* fb3 = (const float*)d_in[14];
    const float* Wda = (const float*)d_in[15]; const float* bda = (const float*)d_in[16];
    const float* Wfa = (const float*)d_in[17]; const float* bfa = (const float*)d_in[18];
    const float* Watt= (const float*)d_in[19]; const float* batt= (const float*)d_in[20];
    const float* W1  = (const float*)d_in[21]; const float* b1  = (const float*)d_in[22];
    const float* W2  = (const float*)d_in[23]; const float* b2  = (const float*)d_in[24];
    const float* W3  = (const float*)d_in[25]; const float* b3  = (const float*)d_in[26];
    const float* Wo  = (const float*)d_in[27]; const float* bo  = (const float*)d_in[28];
    float* out = (float*)d_out;

    float *x, *h1, *h2, *dc, *att, *Am, *w1r, *w2r, *w3r;
    float *fwm1, *fwm2, *fwm3, *hf1, *hf2, *fnn, *fatt, *pair, *fh1, *fh2, *fh3;
    cudaGetSymbolAddress((void**)&x,   g_x);
    cudaGetSymbolAddress((void**)&h1,  g_h1);
    cudaGetSymbolAddress((void**)&h2,  g_h2);
    cudaGetSymbolAddress((void**)&dc,  g_dc);
    cudaGetSymbolAddress((void**)&att, g_att);
    cudaGetSymbolAddress((void**)&Am,  g_Am);
    cudaGetSymbolAddress((void**)&w1r, g_w1r);
    cudaGetSymbolAddress((void**)&w2r, g_w2r);
    cudaGetSymbolAddress((void**)&w3r, g_w3r);
    cudaGetSymbolAddress((void**)&fwm1, g_fwm1);
    cudaGetSymbolAddress((void**)&fwm2, g_fwm2);
    cudaGetSymbolAddress((void**)&fwm3, g_fwm3);
    cudaGetSymbolAddress((void**)&hf1, g_hf1);
    cudaGetSymbolAddress((void**)&hf2, g_hf2);
    cudaGetSymbolAddress((void**)&fnn, g_fnn);
    cudaGetSymbolAddress((void**)&fatt, g_fatt);
    cudaGetSymbolAddress((void**)&pair, g_pair);
    cudaGetSymbolAddress((void**)&fh1, g_fh1);
    cudaGetSymbolAddress((void**)&fh2, g_fh2);
    cudaGetSymbolAddress((void**)&fh3, g_fh3);

    // prep
    embed_k<<<(BATCH * LD * 32 + 255) / 256, 256>>>(drug, emb, x);
    reorder_w<<<(128 * 128 * 4 + 255) / 256, 256>>>(dw1, w1r, 128, 128, 4);
    reorder_w<<<(256 * 128 * 6 + 255) / 256, 256>>>(dw2, w2r, 256, 128, 6);
    reorder_w<<<(512 * 256 * 8 + 255) / 256, 256>>>(dw3, w3r, 512, 256, 8);
    midtap_k<<<(128 * 7   + 255) / 256, 256>>>(fw1, fwm1, 128 * 7);
    midtap_k<<<(256 * 128 + 255) / 256, 256>>>(fw2, fwm2, 256 * 128);
    midtap_k<<<(512 * 256 + 255) / 256, 256>>>(fw3, fwm3, 512 * 256);

    // drug conv stack (implicit GEMM, relu)
    gemm_bt<1><<<dim3(1, (BATCH * L1O) / 128), 256>>>(x,  w1r, db1, h1,
        BATCH * L1O, 128, 4 * 128, L1O, (long)LD * 128, 128);
    gemm_bt<1><<<dim3(2, (BATCH * L2O) / 128), 256>>>(h1, w2r, db2, h2,
        BATCH * L2O, 256, 6 * 128, L2O, (long)L1O * 128, 128);
    gemm_bt<1><<<dim3(4, (BATCH * L3O) / 128), 256>>>(h2, w3r, db3, dc,
        BATCH * L3O, 512, 8 * 256, L3O, (long)L2O * 256, 256);

    // drug_att = drugConv @ Wda^T + bda
    gemm_bt<0><<<dim3(4, (BATCH * L3O) / 128), 256>>>(dc, Wda, bda, att,
        BATCH * L3O, 512, 512, BATCH * L3O, 0L, 512L);

    // feature branch (mid-tap dense layers)
    feat1_k<<<(BATCH * 128) / 256, 256>>>(feature, fwm1, fb1, hf1);
    gemm_bt<1><<<dim3(2, BATCH / 128), 256>>>(hf1, fwm2, fb2, hf2,
        BATCH, 256, 128, BATCH, 0L, 128L);
    gemm_bt<1><<<dim3(4, BATCH / 128), 256>>>(hf2, fwm3, fb3, fnn,
        BATCH, 512, 256, BATCH, 0L, 256L);
    gemm_bt<0><<<dim3(4, BATCH / 128), 256>>>(fnn, Wfa, bfa, fatt,
        BATCH, 512, 512, BATCH, 0L, 512L);

    // s = relu(drug_att + feature_att)
    {
        long total = (long)BATCH * L3O * 512;
        s_relu_k<<<(unsigned)((total + 255) / 256), 256>>>(att, fatt);
    }

    // A = s @ Watt^T + batt
    gemm_bt<0><<<dim3(4, (BATCH * L3O) / 128), 256>>>(att, Watt, batt, Am,
        BATCH * L3O, 512, 512, BATCH * L3O, 0L, 512L);

    // fused gating + max/mean reductions -> pair
    reduce_k<<<BATCH, 512>>>(dc, Am, fnn, pair);

    // FC head (leaky relu)
    gemm_bt<2><<<dim3(8, BATCH / 128), 256>>>(pair, W1, b1, fh1,
        BATCH, 1024, 1024, BATCH, 0L, 1024L);
    gemm_bt<2><<<dim3(8, BATCH / 128), 256>>>(fh1, W2, b2, fh2,
        BATCH, 1024, 1024, BATCH, 0L, 1024L);
    gemm_bt<2><<<dim3(4, BATCH / 128), 256>>>(fh2, W3, b3, fh3,
        BATCH, 512, 1024, BATCH, 0L, 1024L);

    final_k<<<BATCH, 128>>>(fh3, Wo, bo, out);
}

// round 3
// speedup vs baseline: 1.5153x; 1.5153x over previous
#include <cuda_runtime.h>
#include <cuda_bf16.h>
#include <math.h>
#include <stdint.h>

// ---------------- problem constants ----------------
#define BATCH 2048
#define LD    100
#define DIM   128
#define L1O   97
#define L2O   92
#define L3O   85

// ---------------- scratch (device globals; allocation-free) ----------------
__device__ float g_x  [BATCH * LD  * DIM];
__device__ float g_h1 [BATCH * L1O * 128];
__device__ float g_h2 [BATCH * L2O * 256];
__device__ float g_dc [BATCH * L3O * 512];
__device__ float g_att[BATCH * L3O * 512];
__device__ float g_Am [BATCH * L3O * 512];
__device__ float g_w1r[128 * 512];
__device__ float g_w2r[256 * 768];
__device__ float g_w3r[512 * 2048];
__device__ float g_fwm1[128 * 7];
__device__ float g_fwm2[256 * 128];
__device__ float g_fwm3[512 * 256];
__device__ float g_hf1[BATCH * 128];
__device__ float g_hf2[BATCH * 256];
__device__ float g_fnn[BATCH * 512];
__device__ float g_fatt[BATCH * 512];
__device__ float g_pair[BATCH * 1024];
__device__ float g_fh1[BATCH * 1024];
__device__ float g_fh2[BATCH * 1024];
__device__ float g_fh3[BATCH * 512];

// ---------------- helpers ----------------
__device__ __forceinline__ uint32_t smem_u32(const void* p) {
    uint32_t a;
    asm("{ .reg .u64 t; cvta.to.shared.u64 t, %1; cvt.u32.u64 %0, t; }"
        : "=r"(a) : "l"(p));
    return a;
}

__device__ __forceinline__ void ldm4(uint32_t* r, uint32_t saddr) {
    asm volatile("ldmatrix.sync.aligned.m8n8.x4.shared.b16 {%0,%1,%2,%3}, [%4];"
        : "=r"(r[0]), "=r"(r[1]), "=r"(r[2]), "=r"(r[3]) : "r"(saddr));
}

__device__ __forceinline__ void mma16816(float* d, const uint32_t* a,
                                         uint32_t b0, uint32_t b1) {
    asm volatile(
        "mma.sync.aligned.m16n8k16.row.col.f32.bf16.bf16.f32 "
        "{%0,%1,%2,%3}, {%4,%5,%6,%7}, {%8,%9}, {%0,%1,%2,%3};"
        : "+f"(d[0]), "+f"(d[1]), "+f"(d[2]), "+f"(d[3])
        : "r"(a[0]), "r"(a[1]), "r"(a[2]), "r"(a[3]), "r"(b0), "r"(b1));
}

__device__ __forceinline__ uint32_t pack2(float x, float y) {
    __nv_bfloat16 a = __float2bfloat16(x), b = __float2bfloat16(y);
    return (uint32_t)__bfloat16_as_ushort(a) | ((uint32_t)__bfloat16_as_ushort(b) << 16);
}
__device__ __forceinline__ float bf16lo_res(float x) {
    __nv_bfloat16 h = __float2bfloat16(x);
    return x - __bfloat162float(h);
}

// ---------------- mma.sync GEMM: C = act(A * W^T + bias [+ extra]) ----------------
// bf16 hi/lo split (3 MMA passes), fp32 accumulate.
// A row m at: A + (m/Lout)*sOuter + (m%Lout)*sInner (contiguous K floats).
// Requires M%128==0, N%128==0, K%32==0.
#define KT    32
#define RPAD  20                 // 32-bit words per padded row (40 bf16)
#define ARRW  (128 * RPAD)       // words per operand array (2560)
#define BUFW  (4 * ARRW)         // words per buffer (Ah,Al,Bh,Bl)
#define GSMEM (2 * BUFW * 4)     // bytes (81920)

template <int ACT>   // 0 none, 1 relu, 2 leaky, 3 bias+extra+relu
__global__ __launch_bounds__(256, 1)
void gemm_mma(const float* __restrict__ A, const float* __restrict__ W,
              const float* __restrict__ bias, const float* __restrict__ extra,
              float* __restrict__ C,
              int M, int N, int K, int Lout, long sOuter, long sInner, int rowdiv) {
    extern __shared__ uint32_t sw[];
    const uint32_t smb = smem_u32(sw);
    const int tid = threadIdx.x;
    const int wid = tid >> 5, lane = tid & 31;
    const int m0 = blockIdx.y * 128, n0 = blockIdx.x * 128;
    const int wm = wid >> 1, wn = wid & 1;    // warp 32-row quadrant, 64-col half

    // ---- global loader mapping: row lr, 16-float half lc ----
    const int lr = tid >> 1;
    const int lc = (tid & 1) * 16;
    const float* arow = A + (long)((m0 + lr) / Lout) * sOuter
                          + (long)((m0 + lr) % Lout) * sInner + lc;
    const float* brow = W + (long)(n0 + lr) * K + lc;

    // ---- ldmatrix lane base offsets (bytes) ----
    const int laneR = lane & 15;
    const int laneC = (lane >> 4) * 4;   // word col offset within k16
    const uint32_t aBase = smb + 4u * ((uint32_t)(wm * 32 + laneR) * RPAD + laneC);
    const uint32_t bBase = smb + 4u * ((uint32_t)(wn * 64 + laneR) * RPAD + laneC);

    float acc[2][8][4];
#pragma unroll
    for (int i = 0; i < 2; i++)
#pragma unroll
        for (int j = 0; j < 8; j++)
#pragma unroll
            for (int k = 0; k < 4; k++) acc[i][j][k] = 0.f;

    float4 ra[4], rb[4];
    const int T = K / KT;

    // prefetch chunk 0
#pragma unroll
    for (int i = 0; i < 4; i++) {
        ra[i] = *(const float4*)(arow + i * 4);
        rb[i] = *(const float4*)(brow + i * 4);
    }
    // store chunk 0 -> buf 0
    {
        uint32_t* dst = sw + lr * RPAD + (lc >> 1);
#pragma unroll
        for (int p = 0; p < 2; p++) {
            float4 v0 = ra[2 * p], v1 = ra[2 * p + 1];
            uint4 hi = make_uint4(pack2(v0.x, v0.y), pack2(v0.z, v0.w),
                                  pack2(v1.x, v1.y), pack2(v1.z, v1.w));
            uint4 lo = make_uint4(pack2(bf16lo_res(v0.x), bf16lo_res(v0.y)),
                                  pack2(bf16lo_res(v0.z), bf16lo_res(v0.w)),
                                  pack2(bf16lo_res(v1.x), bf16lo_res(v1.y)),
                                  pack2(bf16lo_res(v1.z), bf16lo_res(v1.w)));
            *(uint4*)(dst + p * 4) = hi;
            *(uint4*)(dst + ARRW + p * 4) = lo;
            v0 = rb[2 * p]; v1 = rb[2 * p + 1];
            hi = make_uint4(pack2(v0.x, v0.y), pack2(v0.z, v0.w),
                            pack2(v1.x, v1.y), pack2(v1.z, v1.w));
            lo = make_uint4(pack2(bf16lo_res(v0.x), bf16lo_res(v0.y)),
                            pack2(bf16lo_res(v0.z), bf16lo_res(v0.w)),
                            pack2(bf16lo_res(v1.x), bf16lo_res(v1.y)),
                            pack2(bf16lo_res(v1.z), bf16lo_res(v1.w)));
            *(uint4*)(dst + 2 * ARRW + p * 4) = hi;
            *(uint4*)(dst + 3 * ARRW + p * 4) = lo;
        }
    }
    __syncthreads();

    for (int t = 0; t < T; ++t) {
        // prefetch next chunk into registers
        if (t + 1 < T) {
            const int k0 = (t + 1) * KT;
#pragma unroll
            for (int i = 0; i < 4; i++) {
                ra[i] = *(const float4*)(arow + k0 + i * 4);
                rb[i] = *(const float4*)(brow + k0 + i * 4);
            }
        }

        // compute on buffer t&1
        const uint32_t bufB = (uint32_t)(t & 1) * (BUFW * 4u);
#pragma unroll
        for (int j = 0; j < 2; j++) {                 // two k16 steps
            uint32_t ah[2][4], al[2][4];
#pragma unroll
            for (int mt = 0; mt < 2; mt++) {
                uint32_t a_addr = aBase + bufB + (uint32_t)(mt * 16 * RPAD * 4 + j * 32);
                ldm4(ah[mt], a_addr);
                ldm4(al[mt], a_addr + ARRW * 4u);
            }
#pragma unroll
            for (int nt2 = 0; nt2 < 4; nt2++) {
                uint32_t bh[4], bl[4];
                uint32_t b_addr = bBase + bufB + (uint32_t)(2 * ARRW * 4)
                                + (uint32_t)(nt2 * 16 * RPAD * 4 + j * 32);
                ldm4(bh, b_addr);
                ldm4(bl, b_addr + ARRW * 4u);
#pragma unroll
                for (int mt = 0; mt < 2; mt++) {
                    float* de = acc[mt][2 * nt2];
                    float* dо = acc[mt][2 * nt2 + 1];
                    mma16816(de, ah[mt], bh[0], bh[2]);
                    mma16816(de, ah[mt], bl[0], bl[2]);
                    mma16816(de, al[mt], bh[0], bh[2]);
                    mma16816(dо, ah[mt], bh[1], bh[3]);
                    mma16816(dо, ah[mt], bl[1], bl[3]);
                    mma16816(dо, al[mt], bh[1], bh[3]);
                }
            }
        }

        // split-store next chunk to other buffer
        if (t + 1 < T) {
            uint32_t* dst = sw + ((t + 1) & 1) * BUFW + lr * RPAD + (lc >> 1);
#pragma unroll
            for (int p = 0; p < 2; p++) {
                float4 v0 = ra[2 * p], v1 = ra[2 * p + 1];
                uint4 hi = make_uint4(pack2(v0.x, v0.y), pack2(v0.z, v0.w),
                                      pack2(v1.x, v1.y), pack2(v1.z, v1.w));
                uint4 lo = make_uint4(pack2(bf16lo_res(v0.x), bf16lo_res(v0.y)),
                                      pack2(bf16lo_res(v0.z), bf16lo_res(v0.w)),
                                      pack2(bf16lo_res(v1.x), bf16lo_res(v1.y)),
                                      pack2(bf16lo_res(v1.z), bf16lo_res(v1.w)));
                *(uint4*)(dst + p * 4) = hi;
                *(uint4*)(dst + ARRW + p * 4) = lo;
                v0 = rb[2 * p]; v1 = rb[2 * p + 1];
                hi = make_uint4(pack2(v0.x, v0.y), pack2(v0.z, v0.w),
                                pack2(v1.x, v1.y), pack2(v1.z, v1.w));
                lo = make_uint4(pack2(bf16lo_res(v0.x), bf16lo_res(v0.y)),
                                pack2(bf16lo_res(v0.z), bf16lo_res(v0.w)),
                                pack2(bf16lo_res(v1.x), bf16lo_res(v1.y)),
                                pack2(bf16lo_res(v1.z), bf16lo_res(v1.w)));
                *(uint4*)(dst + 2 * ARRW + p * 4) = hi;
                *(uint4*)(dst + 3 * ARRW + p * 4) = lo;
            }
        }
        __syncthreads();
    }

    // ---- epilogue: registers -> global with bias/activation ----
    const int mrowL = wm * 32 + (lane >> 2);
    const int ncolL = wn * 64 + (lane & 3) * 2;
#pragma unroll
    for (int mt = 0; mt < 2; mt++) {
#pragma unroll
        for (int h = 0; h < 2; h++) {
            const long m = (long)m0 + mrowL + mt * 16 + h * 8;
            float* crow = C + m * (long)N;
            const float* erow = (ACT == 3) ? (extra + (long)(m / rowdiv) * N) : nullptr;
#pragma unroll
            for (int nt = 0; nt < 8; nt++) {
                const int n = n0 + ncolL + nt * 8;
                float vx = acc[mt][nt][2 * h]     + bias[n];
                float vy = acc[mt][nt][2 * h + 1] + bias[n + 1];
                if (ACT == 3) { vx += erow[n]; vy += erow[n + 1]; }
                if (ACT == 1 || ACT == 3) {
                    vx = fmaxf(vx, 0.f); vy = fmaxf(vy, 0.f);
                } else if (ACT == 2) {
                    vx = vx > 0.f ? vx : 0.01f * vx;
                    vy = vy > 0.f ? vy : 0.01f * vy;
                }
                float2 v = make_float2(vx, vy);
                *(float2*)(crow + n) = v;
            }
        }
    }
}

// ---------------- small prep / glue kernels ----------------
__global__ void embed_k(const int* __restrict__ drug, const float* __restrict__ emb,
                        float* __restrict__ x) {
    int idx = blockIdx.x * blockDim.x + threadIdx.x;
    const int total = BATCH * LD * (DIM / 4);
    if (idx >= total) return;
    int d4 = idx & 31;
    int bl = idx >> 5;
    int tok = drug[bl];
    ((float4*)x)[(size_t)bl * 32 + d4] = ((const float4*)emb)[(size_t)tok * 32 + d4];
}

__global__ void reorder_w(const float* __restrict__ w, float* __restrict__ wr,
                          int O, int Ci, int Kw) {
    int idx = blockIdx.x * blockDim.x + threadIdx.x;
    int total = O * Ci * Kw;
    if (idx >= total) return;
    int o = idx / (Ci * Kw);
    int rr = idx - o * (Ci * Kw);
    int i = rr / Kw;
    int k = rr - i * Kw;
    wr[(size_t)o * Ci * Kw + k * Ci + i] = w[idx];
}

__global__ void midtap_k(const float* __restrict__ w, float* __restrict__ wr, int total) {
    int idx = blockIdx.x * blockDim.x + threadIdx.x;
    if (idx >= total) return;
    wr[idx] = w[idx * 3 + 1];
}

__global__ void feat1_k(const float* __restrict__ feat, const float* __restrict__ wm,
                        const float* __restrict__ bias, float* __restrict__ out) {
    int idx = blockIdx.x * blockDim.x + threadIdx.x;
    if (idx >= BATCH * 128) return;
    int b = idx >> 7, o = idx & 127;
    float s = bias[o];
#pragma unroll
    for (int i = 0; i < 7; i++) s = fmaf(feat[b * 7 + i], wm[o * 7 + i], s);
    out[idx] = fmaxf(s, 0.f);
}

__global__ void reduce_k(const float* __restrict__ dc, const float* __restrict__ Am,
                         const float* __restrict__ fnn, float* __restrict__ pair) {
    int b = blockIdx.x;
    int c = threadIdx.x;
    const float* dp = dc + (size_t)b * L3O * 512 + c;
    const float* ap = Am + (size_t)b * L3O * 512 + c;
    float mx = -1e30f, smv = 0.f;
#pragma unroll 5
    for (int l = 0; l < L3O; l++) {
        float a = ap[(size_t)l * 512];
        float d = dp[(size_t)l * 512];
        float sg = 1.f / (1.f + expf(-a));
        mx = fmaxf(mx, d * (0.5f + sg));
        smv += a;
    }
    float fsig = 1.f / (1.f + expf(-smv * (1.0f / L3O)));
    pair[(size_t)b * 1024 + c]       = mx;
    pair[(size_t)b * 1024 + 512 + c] = fnn[(size_t)b * 512 + c] * (0.5f + fsig);
}

__global__ void final_k(const float* __restrict__ h3, const float* __restrict__ Wo,
                        const float* __restrict__ bo, float* __restrict__ out) {
    int b = blockIdx.x;
    int t = threadIdx.x;
    float s = 0.f;
#pragma unroll
    for (int c = t; c < 512; c += 128) s = fmaf(h3[(size_t)b * 512 + c], Wo[c], s);
#pragma unroll
    for (int o = 16; o > 0; o >>= 1) s += __shfl_down_sync(0xffffffffu, s, o);
    __shared__ float red[4];
    if ((t & 31) == 0) red[t >> 5] = s;
    __syncthreads();
    if (t == 0) out[b] = red[0] + red[1] + red[2] + red[3] + bo[0];
}

// ---------------- host launch ----------------
extern "C" void kernel_launch(void* const* d_in, const int* in_sizes, int n_in,
                              void* d_out, int out_size) {
    const int*   drug    = (const int*)  d_in[0];
    const float* feature = (const float*)d_in[1];
    const float* emb     = (const float*)d_in[2];
    const float* dw1 = (const float*)d_in[3];  const float* db1 = (const float*)d_in[4];
    const float* dw2 = (const float*)d_in[5];  const float* db2 = (const float*)d_in[6];
    const float* dw3 = (const float*)d_in[7];  const float* db3 = (const float*)d_in[8];
    const float* fw1 = (const float*)d_in[9];  const float* fb1 = (const float*)d_in[10];
    const float* fw2 = (const float*)d_in[11]; const float* fb2 = (const float*)d_in[12];
    const float* fw3 = (const float*)d_in[13]; const float* fb3 = (const float*)d_in[14];
    const float* Wda = (const float*)d_in[15]; const float* bda = (const float*)d_in[16];
    const float* Wfa = (const float*)d_in[17]; const float* bfa = (const float*)d_in[18];
    const float* Watt= (const float*)d_in[19]; const float* batt= (const float*)d_in[20];
    const float* W1  = (const float*)d_in[21]; const float* b1  = (const float*)d_in[22];
    const float* W2  = (const float*)d_in[23]; const float* b2  = (const float*)d_in[24];
    const float* W3  = (const float*)d_in[25]; const float* b3  = (const float*)d_in[26];
    const float* Wo  = (const float*)d_in[27]; const float* bo  = (const float*)d_in[28];
    float* out = (float*)d_out;

    float *x, *h1, *h2, *dc, *att, *Am, *w1r, *w2r, *w3r;
    float *fwm1, *fwm2, *fwm3, *hf1, *hf2, *fnn, *fatt, *pair, *fh1, *fh2, *fh3;
    cudaGetSymbolAddress((void**)&x,   g_x);
    cudaGetSymbolAddress((void**)&h1,  g_h1);
    cudaGetSymbolAddress((void**)&h2,  g_h2);
    cudaGetSymbolAddress((void**)&dc,  g_dc);
    cudaGetSymbolAddress((void**)&att, g_att);
    cudaGetSymbolAddress((void**)&Am,  g_Am);
    cudaGetSymbolAddress((void**)&w1r, g_w1r);
    cudaGetSymbolAddress((void**)&w2r, g_w2r);
    cudaGetSymbolAddress((void**)&w3r, g_w3r);
    cudaGetSymbolAddress((void**)&fwm1, g_fwm1);
    cudaGetSymbolAddress((void**)&fwm2, g_fwm2);
    cudaGetSymbolAddress((void**)&fwm3, g_fwm3);
    cudaGetSymbolAddress((void**)&hf1, g_hf1);
    cudaGetSymbolAddress((void**)&hf2, g_hf2);
    cudaGetSymbolAddress((void**)&fnn, g_fnn);
    cudaGetSymbolAddress((void**)&fatt, g_fatt);
    cudaGetSymbolAddress((void**)&pair, g_pair);
    cudaGetSymbolAddress((void**)&fh1, g_fh1);
    cudaGetSymbolAddress((void**)&fh2, g_fh2);
    cudaGetSymbolAddress((void**)&fh3, g_fh3);

    cudaFuncSetAttribute(gemm_mma<0>, cudaFuncAttributeMaxDynamicSharedMemorySize, GSMEM);
    cudaFuncSetAttribute(gemm_mma<1>, cudaFuncAttributeMaxDynamicSharedMemorySize, GSMEM);
    cudaFuncSetAttribute(gemm_mma<2>, cudaFuncAttributeMaxDynamicSharedMemorySize, GSMEM);
    cudaFuncSetAttribute(gemm_mma<3>, cudaFuncAttributeMaxDynamicSharedMemorySize, GSMEM);

    // prep
    embed_k<<<(BATCH * LD * 32 + 255) / 256, 256>>>(drug, emb, x);
    reorder_w<<<(128 * 128 * 4 + 255) / 256, 256>>>(dw1, w1r, 128, 128, 4);
    reorder_w<<<(256 * 128 * 6 + 255) / 256, 256>>>(dw2, w2r, 256, 128, 6);
    reorder_w<<<(512 * 256 * 8 + 255) / 256, 256>>>(dw3, w3r, 512, 256, 8);
    midtap_k<<<(128 * 7   + 255) / 256, 256>>>(fw1, fwm1, 128 * 7);
    midtap_k<<<(256 * 128 + 255) / 256, 256>>>(fw2, fwm2, 256 * 128);
    midtap_k<<<(512 * 256 + 255) / 256, 256>>>(fw3, fwm3, 512 * 256);

    // feature branch first (fatt needed by fused att epilogue)
    feat1_k<<<(BATCH * 128) / 256, 256>>>(feature, fwm1, fb1, hf1);
    gemm_mma<1><<<dim3(2, BATCH / 128), 256, GSMEM>>>(hf1, fwm2, fb2, nullptr, hf2,
        BATCH, 256, 128, BATCH, 0L, 128L, 1);
    gemm_mma<1><<<dim3(4, BATCH / 128), 256, GSMEM>>>(hf2, fwm3, fb3, nullptr, fnn,
        BATCH, 512, 256, BATCH, 0L, 256L, 1);
    gemm_mma<0><<<dim3(4, BATCH / 128), 256, GSMEM>>>(fnn, Wfa, bfa, nullptr, fatt,
        BATCH, 512, 512, BATCH, 0L, 512L, 1);

    // drug conv stack (implicit GEMM, relu)
    gemm_mma<1><<<dim3(1, (BATCH * L1O) / 128), 256, GSMEM>>>(x,  w1r, db1, nullptr, h1,
        BATCH * L1O, 128, 4 * 128, L1O, (long)LD * 128, 128L, 1);
    gemm_mma<1><<<dim3(2, (BATCH * L2O) / 128), 256, GSMEM>>>(h1, w2r, db2, nullptr, h2,
        BATCH * L2O, 256, 6 * 128, L2O, (long)L1O * 128, 128L, 1);
    gemm_mma<1><<<dim3(4, (BATCH * L3O) / 128), 256, GSMEM>>>(h2, w3r, db3, nullptr, dc,
        BATCH * L3O, 512, 8 * 256, L3O, (long)L2O * 256, 256L, 1);

    // s = relu(dc @ Wda^T + bda + fatt[b]) fused
    gemm_mma<3><<<dim3(4, (BATCH * L3O) / 128), 256, GSMEM>>>(dc, Wda, bda, fatt, att,
        BATCH * L3O, 512, 512, BATCH * L3O, 0L, 512L, L3O);

    // A = s @ Watt^T + batt
    gemm_mma<0><<<dim3(4, (BATCH * L3O) / 128), 256, GSMEM>>>(att, Watt, batt, nullptr, Am,
        BATCH * L3O, 512, 512, BATCH * L3O, 0L, 512L, 1);

    // fused gating + max/mean reductions -> pair
    reduce_k<<<BATCH, 512>>>(dc, Am, fnn, pair);

    // FC head (leaky relu)
    gemm_mma<2><<<dim3(8, BATCH / 128), 256, GSMEM>>>(pair, W1, b1, nullptr, fh1,
        BATCH, 1024, 1024, BATCH, 0L, 1024L, 1);
    gemm_mma<2><<<dim3(8, BATCH / 128), 256, GSMEM>>>(fh1, W2, b2, nullptr, fh2,
        BATCH, 1024, 1024, BATCH, 0L, 1024L, 1);
    gemm_mma<2><<<dim3(4, BATCH / 128), 256, GSMEM>>>(fh2, W3, b3, nullptr, fh3,
        BATCH, 512, 1024, BATCH, 0L, 1024L, 1);

    final_k<<<BATCH, 128>>>(fh3, Wo, bo, out);
}

// round 4
// speedup vs baseline: 1.6608x; 1.0960x over previous
#include <cuda_runtime.h>
#include <cuda_bf16.h>
#include <math.h>
#include <stdint.h>

// ---------------- problem constants ----------------
#define BATCH 2048
#define LD    100
#define DIM   128
#define L1O   97
#define L2O   92
#define L3O   85

typedef __nv_bfloat16 bf16;

// ---------------- scratch (device globals; allocation-free) ----------------
// bf16 hi/lo activation buffers
__device__ bf16 g_xh [BATCH * LD  * DIM];   __device__ bf16 g_xl [BATCH * LD  * DIM];
__device__ bf16 g_h1h[BATCH * L1O * 128];   __device__ bf16 g_h1l[BATCH * L1O * 128];
__device__ bf16 g_h2h[BATCH * L2O * 256];   __device__ bf16 g_h2l[BATCH * L2O * 256];
__device__ bf16 g_dch[BATCH * L3O * 512];   __device__ bf16 g_dcl[BATCH * L3O * 512];
__device__ bf16 g_atth[BATCH * L3O * 512];  __device__ bf16 g_attl[BATCH * L3O * 512];
__device__ bf16 g_hf1h[BATCH * 128];        __device__ bf16 g_hf1l[BATCH * 128];
__device__ bf16 g_hf2h[BATCH * 256];        __device__ bf16 g_hf2l[BATCH * 256];
__device__ bf16 g_fnnh[BATCH * 512];        __device__ bf16 g_fnnl[BATCH * 512];
__device__ bf16 g_pairh[BATCH * 1024];      __device__ bf16 g_pairl[BATCH * 1024];
__device__ bf16 g_fh1h[BATCH * 1024];       __device__ bf16 g_fh1l[BATCH * 1024];
__device__ bf16 g_fh2h[BATCH * 1024];       __device__ bf16 g_fh2l[BATCH * 1024];
// fp32 buffers (consumed by scalar kernels)
__device__ float g_dcf[BATCH * L3O * 512];
__device__ float g_Amf[BATCH * L3O * 512];
__device__ float g_fnnf[BATCH * 512];
__device__ float g_fattf[BATCH * 512];
__device__ float g_fh3f[BATCH * 512];
__device__ float g_fwm1[128 * 7];
// bf16 hi/lo weights
__device__ bf16 g_w1rh[128 * 512];   __device__ bf16 g_w1rl[128 * 512];
__device__ bf16 g_w2rh[256 * 768];   __device__ bf16 g_w2rl[256 * 768];
__device__ bf16 g_w3rh[512 * 2048];  __device__ bf16 g_w3rl[512 * 2048];
__device__ bf16 g_fwm2h[256 * 128];  __device__ bf16 g_fwm2l[256 * 128];
__device__ bf16 g_fwm3h[512 * 256];  __device__ bf16 g_fwm3l[512 * 256];
__device__ bf16 g_Wdah[512 * 512];   __device__ bf16 g_Wdal[512 * 512];
__device__ bf16 g_Wfah[512 * 512];   __device__ bf16 g_Wfal[512 * 512];
__device__ bf16 g_Watth[512 * 512];  __device__ bf16 g_Wattl[512 * 512];
__device__ bf16 g_W1h[1024 * 1024];  __device__ bf16 g_W1l[1024 * 1024];
__device__ bf16 g_W2h[1024 * 1024];  __device__ bf16 g_W2l[1024 * 1024];
__device__ bf16 g_W3h[512 * 1024];   __device__ bf16 g_W3l[512 * 1024];

// ---------------- helpers ----------------
__device__ __forceinline__ uint32_t smem_u32(const void* p) {
    uint32_t a;
    asm("{ .reg .u64 t; cvta.to.shared.u64 t, %1; cvt.u32.u64 %0, t; }"
        : "=r"(a) : "l"(p));
    return a;
}
__device__ __forceinline__ void ldm4(uint32_t* r, uint32_t saddr) {
    asm volatile("ldmatrix.sync.aligned.m8n8.x4.shared.b16 {%0,%1,%2,%3}, [%4];"
        : "=r"(r[0]), "=r"(r[1]), "=r"(r[2]), "=r"(r[3]) : "r"(saddr));
}
__device__ __forceinline__ void mma16816(float* d, const uint32_t* a,
                                         uint32_t b0, uint32_t b1) {
    asm volatile(
        "mma.sync.aligned.m16n8k16.row.col.f32.bf16.bf16.f32 "
        "{%0,%1,%2,%3}, {%4,%5,%6,%7}, {%8,%9}, {%0,%1,%2,%3};"
        : "+f"(d[0]), "+f"(d[1]), "+f"(d[2]), "+f"(d[3])
        : "r"(a[0]), "r"(a[1]), "r"(a[2]), "r"(a[3]), "r"(b0), "r"(b1));
}
#define CPA16(dst, src) \
    asm volatile("cp.async.cg.shared.global [%0], [%1], 16;" :: "r"(dst), "l"(src) : "memory")
#define CPCOMMIT() asm volatile("cp.async.commit_group;" ::: "memory")
template <int NW> __device__ __forceinline__ void cpwait() {
    asm volatile("cp.async.wait_group %0;" :: "n"(NW) : "memory");
}

__device__ __forceinline__ uint32_t pack2(float x, float y) {
    bf16 a = __float2bfloat16(x), b = __float2bfloat16(y);
    return (uint32_t)__bfloat16_as_ushort(a) | ((uint32_t)__bfloat16_as_ushort(b) << 16);
}
__device__ __forceinline__ float bf16lo_res(float x) {
    return x - __bfloat162float(__float2bfloat16(x));
}
__device__ __forceinline__ void split1(float v, bf16& h, bf16& l) {
    h = __float2bfloat16(v);
    l = __float2bfloat16(v - __bfloat162float(h));
}

// ---------------- GEMM: C = act(Ahl * Whl^T + bias [+ extra]) ----------------
// CTA tile 256(M)x128(N), 8 warps (4x2), warp tile 64x64. K staged by 32, cp.async.
// bf16 hi/lo operands pre-split in global. 3 MMA passes: hi*hi + lo*hi + hi*lo.
// A row m at: Ah/Al + (m/Lout)*sOuter + (m%Lout)*sInner.
// Requires M%256==0, N%128==0, K%32==0.
#define ROWB   80u                 // padded row pitch bytes (40 bf16)
#define AREG   20480u              // 256 rows * 80B
#define BREG   10240u              // 128 rows * 80B
#define STG    61440u              // Ah+Al+Bh+Bl
#define GSMEM  (2 * 61440)

template <int ACT, int OM>  // ACT: 0 none,1 relu,2 leaky,3 relu(bias+extra); OM: 0 f32,1 hilo,2 both
__global__ __launch_bounds__(256, 1)
void gemm2(const bf16* __restrict__ Ah, const bf16* __restrict__ Al,
           const bf16* __restrict__ Wh, const bf16* __restrict__ Wl,
           const float* __restrict__ bias, const float* __restrict__ extra,
           float* __restrict__ Cf, bf16* __restrict__ Ch, bf16* __restrict__ Cl,
           int N, int K, int Lout, long sOuter, long sInner, int rowdiv) {
    extern __shared__ char sm[];
    const uint32_t smb = smem_u32(sm);
    const int tid = threadIdx.x;
    const int wid = tid >> 5, lane = tid & 31;
    const int m0 = blockIdx.y * 256, n0 = blockIdx.x * 128;
    const int wm = wid >> 1, wn = wid & 1;

    // loader pointers
    const int mrow = m0 + tid;
    const long aoff = (long)(mrow / Lout) * sOuter + (long)(mrow % Lout) * sInner;
    const bf16* aH = Ah + aoff;
    const bf16* aL = Al + aoff;
    const int brow = n0 + (tid >> 1);
    const bf16* bH = Wh + (long)brow * K;
    const bf16* bL = Wl + (long)brow * K;
    const int bseg = (tid & 1) * 2;

    const uint32_t aDst = smb + (uint32_t)tid * ROWB;
    const uint32_t bDst = smb + 2u * AREG + (uint32_t)(tid >> 1) * ROWB + (uint32_t)bseg * 16u;

    // ldmatrix bases
    const int laneR = lane & 15;
    const uint32_t laneC = (uint32_t)(lane >> 4) * 16u;
    const uint32_t aBase = smb + (uint32_t)(wm * 64 + laneR) * ROWB + laneC;
    const uint32_t bBase = smb + 2u * AREG + (uint32_t)(wn * 64 + laneR) * ROWB + laneC;

    float acc[4][8][4];
#pragma unroll
    for (int i = 0; i < 4; i++)
#pragma unroll
        for (int j = 0; j < 8; j++)
#pragma unroll
            for (int k = 0; k < 4; k++) acc[i][j][k] = 0.f;

    const int T = K / 32;

    // issue stage 0
    {
        const uint32_t sb = 0;
#pragma unroll
        for (int s = 0; s < 4; s++) CPA16(aDst + sb + s * 16u, aH + s * 8);
#pragma unroll
        for (int s = 0; s < 4; s++) CPA16(aDst + sb + AREG + s * 16u, aL + s * 8);
#pragma unroll
        for (int s = 0; s < 2; s++) CPA16(bDst + sb + s * 16u, bH + (bseg + s) * 8);
#pragma unroll
        for (int s = 0; s < 2; s++) CPA16(bDst + sb + BREG + s * 16u, bL + (bseg + s) * 8);
        CPCOMMIT();
    }

    for (int t = 0; t < T; ++t) {
        if (t + 1 < T) {
            const int k0 = (t + 1) * 32;
            const uint32_t sb = (uint32_t)((t + 1) & 1) * STG;
#pragma unroll
            for (int s = 0; s < 4; s++) CPA16(aDst + sb + s * 16u, aH + k0 + s * 8);
#pragma unroll
            for (int s = 0; s < 4; s++) CPA16(aDst + sb + AREG + s * 16u, aL + k0 + s * 8);
#pragma unroll
            for (int s = 0; s < 2; s++) CPA16(bDst + sb + s * 16u, bH + k0 + (bseg + s) * 8);
#pragma unroll
            for (int s = 0; s < 2; s++) CPA16(bDst + sb + BREG + s * 16u, bL + k0 + (bseg + s) * 8);
            CPCOMMIT();
            cpwait<1>();
        } else {
            cpwait<0>();
        }
        __syncthreads();

        const uint32_t soff = (uint32_t)(t & 1) * STG;
#pragma unroll
        for (int j = 0; j < 2; j++) {
            const uint32_t ja = soff + (uint32_t)j * 32u;
            uint32_t ah[4][4], al[4][4], bb[4][4];
#pragma unroll
            for (int mt = 0; mt < 4; mt++) {
                ldm4(ah[mt], aBase + ja + (uint32_t)mt * (16u * ROWB));
                ldm4(al[mt], aBase + ja + (uint32_t)mt * (16u * ROWB) + AREG);
            }
#pragma unroll
            for (int nt = 0; nt < 4; nt++)
                ldm4(bb[nt], bBase + ja + (uint32_t)nt * (16u * ROWB));
            // pass 1: hi*hi, pass 2: lo*hi
#pragma unroll
            for (int nt = 0; nt < 4; nt++)
#pragma unroll
                for (int mt = 0; mt < 4; mt++) {
                    mma16816(acc[mt][2 * nt],     ah[mt], bb[nt][0], bb[nt][2]);
                    mma16816(acc[mt][2 * nt + 1], ah[mt], bb[nt][1], bb[nt][3]);
                    mma16816(acc[mt][2 * nt],     al[mt], bb[nt][0], bb[nt][2]);
                    mma16816(acc[mt][2 * nt + 1], al[mt], bb[nt][1], bb[nt][3]);
                }
            // pass 3: hi*lo
#pragma unroll
            for (int nt = 0; nt < 4; nt++)
                ldm4(bb[nt], bBase + ja + (uint32_t)nt * (16u * ROWB) + BREG);
#pragma unroll
            for (int nt = 0; nt < 4; nt++)
#pragma unroll
                for (int mt = 0; mt < 4; mt++) {
                    mma16816(acc[mt][2 * nt],     ah[mt], bb[nt][0], bb[nt][2]);
                    mma16816(acc[mt][2 * nt + 1], ah[mt], bb[nt][1], bb[nt][3]);
                }
        }
        __syncthreads();
    }

    // ---- epilogue ----
    const int lr2 = lane >> 2;
    const int lc2 = (lane & 3) * 2;
#pragma unroll
    for (int mt = 0; mt < 4; mt++) {
#pragma unroll
        for (int h = 0; h < 2; h++) {
            const long m = (long)m0 + wm * 64 + mt * 16 + h * 8 + lr2;
            const long rowb = m * (long)N;
            const float* erow = (ACT == 3) ? (extra + (long)(m / rowdiv) * N) : nullptr;
#pragma unroll
            for (int nt2 = 0; nt2 < 8; nt2++) {
                const int n = n0 + wn * 64 + nt2 * 8 + lc2;
                float vx = acc[mt][nt2][2 * h]     + bias[n];
                float vy = acc[mt][nt2][2 * h + 1] + bias[n + 1];
                if (ACT == 3) { vx += erow[n]; vy += erow[n + 1]; }
                if (ACT == 1 || ACT == 3) {
                    vx = fmaxf(vx, 0.f); vy = fmaxf(vy, 0.f);
                } else if (ACT == 2) {
                    vx = vx > 0.f ? vx : 0.01f * vx;
                    vy = vy > 0.f ? vy : 0.01f * vy;
                }
                if (OM == 0 || OM == 2)
                    *(float2*)(Cf + rowb + n) = make_float2(vx, vy);
                if (OM == 1 || OM == 2) {
                    *(uint32_t*)(Ch + rowb + n) = pack2(vx, vy);
                    *(uint32_t*)(Cl + rowb + n) = pack2(bf16lo_res(vx), bf16lo_res(vy));
                }
            }
        }
    }
}

// ---------------- prep / glue kernels ----------------
__global__ void embed_split(const int* __restrict__ drug, const float* __restrict__ emb,
                            bf16* __restrict__ xh, bf16* __restrict__ xl) {
    int idx = blockIdx.x * blockDim.x + threadIdx.x;   // one float4
    const int total = BATCH * LD * (DIM / 4);
    if (idx >= total) return;
    int d4 = idx & 31;
    int bl = idx >> 5;
    int tok = drug[bl];
    float4 v = ((const float4*)emb)[(size_t)tok * 32 + d4];
    size_t pos = (size_t)bl * 128 + d4 * 4;
    uint2 hi = make_uint2(pack2(v.x, v.y), pack2(v.z, v.w));
    uint2 lo = make_uint2(pack2(bf16lo_res(v.x), bf16lo_res(v.y)),
                          pack2(bf16lo_res(v.z), bf16lo_res(v.w)));
    *(uint2*)(xh + pos) = hi;
    *(uint2*)(xl + pos) = lo;
}

__global__ void reorder_w_split(const float* __restrict__ w, bf16* __restrict__ wh,
                                bf16* __restrict__ wl, int O, int Ci, int Kw) {
    int idx = blockIdx.x * blockDim.x + threadIdx.x;
    int total = O * Ci * Kw;
    if (idx >= total) return;
    int o = idx / (Ci * Kw);
    int rr = idx - o * (Ci * Kw);
    int i = rr / Kw;
    int k = rr - i * Kw;
    size_t t = (size_t)o * Ci * Kw + k * Ci + i;
    split1(w[idx], wh[t], wl[t]);
}

__global__ void midtap_split(const float* __restrict__ w, bf16* __restrict__ wh,
                             bf16* __restrict__ wl, int total) {
    int idx = blockIdx.x * blockDim.x + threadIdx.x;
    if (idx >= total) return;
    split1(w[idx * 3 + 1], wh[idx], wl[idx]);
}

__global__ void midtap_f32(const float* __restrict__ w, float* __restrict__ wr, int total) {
    int idx = blockIdx.x * blockDim.x + threadIdx.x;
    if (idx >= total) return;
    wr[idx] = w[idx * 3 + 1];
}

__global__ void split_plain(const float* __restrict__ w, bf16* __restrict__ wh,
                            bf16* __restrict__ wl, int total) {
    int idx = blockIdx.x * blockDim.x + threadIdx.x;
    if (idx >= total) return;
    split1(w[idx], wh[idx], wl[idx]);
}

__global__ void feat1_k(const float* __restrict__ feat, const float* __restrict__ wm,
                        const float* __restrict__ bias,
                        bf16* __restrict__ oh, bf16* __restrict__ ol) {
    int idx = blockIdx.x * blockDim.x + threadIdx.x;
    if (idx >= BATCH * 128) return;
    int b = idx >> 7, o = idx & 127;
    float s = bias[o];
#pragma unroll
    for (int i = 0; i < 7; i++) s = fmaf(feat[b * 7 + i], wm[o * 7 + i], s);
    s = fmaxf(s, 0.f);
    split1(s, oh[idx], ol[idx]);
}

__global__ void reduce_k(const float* __restrict__ dc, const float* __restrict__ Am,
                         const float* __restrict__ fnn,
                         bf16* __restrict__ ph, bf16* __restrict__ pl) {
    int b = blockIdx.x;
    int c = threadIdx.x;
    const float* dp = dc + (size_t)b * L3O * 512 + c;
    const float* ap = Am + (size_t)b * L3O * 512 + c;
    float mx = -1e30f, smv = 0.f;
#pragma unroll 5
    for (int l = 0; l < L3O; l++) {
        float a = ap[(size_t)l * 512];
        float d = dp[(size_t)l * 512];
        float sg = 1.f / (1.f + expf(-a));
        mx = fmaxf(mx, d * (0.5f + sg));
        smv += a;
    }
    float fsig = 1.f / (1.f + expf(-smv * (1.0f / L3O)));
    float vf = fnn[(size_t)b * 512 + c] * (0.5f + fsig);
    split1(mx, ph[(size_t)b * 1024 + c],       pl[(size_t)b * 1024 + c]);
    split1(vf, ph[(size_t)b * 1024 + 512 + c], pl[(size_t)b * 1024 + 512 + c]);
}

__global__ void final_k(const float* __restrict__ h3, const float* __restrict__ Wo,
                        const float* __restrict__ bo, float* __restrict__ out) {
    int b = blockIdx.x;
    int t = threadIdx.x;
    float s = 0.f;
#pragma unroll
    for (int c = t; c < 512; c += 128) s = fmaf(h3[(size_t)b * 512 + c], Wo[c], s);
#pragma unroll
    for (int o = 16; o > 0; o >>= 1) s += __shfl_down_sync(0xffffffffu, s, o);
    __shared__ float red[4];
    if ((t & 31) == 0) red[t >> 5] = s;
    __syncthreads();
    if (t == 0) out[b] = red[0] + red[1] + red[2] + red[3] + bo[0];
}

// ---------------- host launch ----------------
#define GADDR(p, sym) cudaGetSymbolAddress((void**)&p, sym)

extern "C" void kernel_launch(void* const* d_in, const int* in_sizes, int n_in,
                              void* d_out, int out_size) {
    const int*   drug    = (const int*)  d_in[0];
    const float* feature = (const float*)d_in[1];
    const float* emb     = (const float*)d_in[2];
    const float* dw1 = (const float*)d_in[3];  const float* db1 = (const float*)d_in[4];
    const float* dw2 = (const float*)d_in[5];  const float* db2 = (const float*)d_in[6];
    const float* dw3 = (const float*)d_in[7];  const float* db3 = (const float*)d_in[8];
    const float* fw1 = (const float*)d_in[9];  const float* fb1 = (const float*)d_in[10];
    const float* fw2 = (const float*)d_in[11]; const float* fb2 = (const float*)d_in[12];
    const float* fw3 = (const float*)d_in[13]; const float* fb3 = (const float*)d_in[14];
    const float* Wda = (const float*)d_in[15]; const float* bda = (const float*)d_in[16];
    const float* Wfa = (const float*)d_in[17]; const float* bfa = (const float*)d_in[18];
    const float* Watt= (const float*)d_in[19]; const float* batt= (const float*)d_in[20];
    const float* W1  = (const float*)d_in[21]; const float* b1  = (const float*)d_in[22];
    const float* W2  = (const float*)d_in[23]; const float* b2  = (const float*)d_in[24];
    const float* W3  = (const float*)d_in[25]; const float* b3  = (const float*)d_in[26];
    const float* Wo  = (const float*)d_in[27]; const float* bo  = (const float*)d_in[28];
    float* out = (float*)d_out;

    bf16 *xh,*xl,*h1h,*h1l,*h2h,*h2l,*dch,*dcl,*atth,*attl;
    bf16 *hf1h,*hf1l,*hf2h,*hf2l,*fnnh,*fnnl,*pairh,*pairl,*fh1h,*fh1l,*fh2h,*fh2l;
    bf16 *w1rh,*w1rl,*w2rh,*w2rl,*w3rh,*w3rl,*fwm2h,*fwm2l,*fwm3h,*fwm3l;
    bf16 *Wdah,*Wdal,*Wfah,*Wfal,*Watth,*Wattl,*W1h,*W1l,*W2h,*W2l,*W3h,*W3l;
    float *dcf,*Amf,*fnnf,*fattf,*fh3f,*fwm1;
    GADDR(xh, g_xh); GADDR(xl, g_xl);
    GADDR(h1h, g_h1h); GADDR(h1l, g_h1l);
    GADDR(h2h, g_h2h); GADDR(h2l, g_h2l);
    GADDR(dch, g_dch); GADDR(dcl, g_dcl);
    GADDR(atth, g_atth); GADDR(attl, g_attl);
    GADDR(hf1h, g_hf1h); GADDR(hf1l, g_hf1l);
    GADDR(hf2h, g_hf2h); GADDR(hf2l, g_hf2l);
    GADDR(fnnh, g_fnnh); GADDR(fnnl, g_fnnl);
    GADDR(pairh, g_pairh); GADDR(pairl, g_pairl);
    GADDR(fh1h, g_fh1h); GADDR(fh1l, g_fh1l);
    GADDR(fh2h, g_fh2h); GADDR(fh2l, g_fh2l);
    GADDR(w1rh, g_w1rh); GADDR(w1rl, g_w1rl);
    GADDR(w2rh, g_w2rh); GADDR(w2rl, g_w2rl);
    GADDR(w3rh, g_w3rh); GADDR(w3rl, g_w3rl);
    GADDR(fwm2h, g_fwm2h); GADDR(fwm2l, g_fwm2l);
    GADDR(fwm3h, g_fwm3h); GADDR(fwm3l, g_fwm3l);
    GADDR(Wdah, g_Wdah); GADDR(Wdal, g_Wdal);
    GADDR(Wfah, g_Wfah); GADDR(Wfal, g_Wfal);
    GADDR(Watth, g_Watth); GADDR(Wattl, g_Wattl);
    GADDR(W1h, g_W1h); GADDR(W1l, g_W1l);
    GADDR(W2h, g_W2h); GADDR(W2l, g_W2l);
    GADDR(W3h, g_W3h); GADDR(W3l, g_W3l);
    GADDR(dcf, g_dcf); GADDR(Amf, g_Amf);
    GADDR(fnnf, g_fnnf); GADDR(fattf, g_fattf);
    GADDR(fh3f, g_fh3f); GADDR(fwm1, g_fwm1);

    cudaFuncSetAttribute(gemm2<0,0>, cudaFuncAttributeMaxDynamicSharedMemorySize, GSMEM);
    cudaFuncSetAttribute(gemm2<1,1>, cudaFuncAttributeMaxDynamicSharedMemorySize, GSMEM);
    cudaFuncSetAttribute(gemm2<1,2>, cudaFuncAttributeMaxDynamicSharedMemorySize, GSMEM);
    cudaFuncSetAttribute(gemm2<3,1>, cudaFuncAttributeMaxDynamicSharedMemorySize, GSMEM);
    cudaFuncSetAttribute(gemm2<2,1>, cudaFuncAttributeMaxDynamicSharedMemorySize, GSMEM);
    cudaFuncSetAttribute(gemm2<2,0>, cudaFuncAttributeMaxDynamicSharedMemorySize, GSMEM);

    // ---- prep (split everything once) ----
    embed_split<<<(BATCH * LD * 32 + 255) / 256, 256>>>(drug, emb, xh, xl);
    reorder_w_split<<<(128 * 128 * 4 + 255) / 256, 256>>>(dw1, w1rh, w1rl, 128, 128, 4);
    reorder_w_split<<<(256 * 128 * 6 + 255) / 256, 256>>>(dw2, w2rh, w2rl, 256, 128, 6);
    reorder_w_split<<<(512 * 256 * 8 + 255) / 256, 256>>>(dw3, w3rh, w3rl, 512, 256, 8);
    midtap_f32  <<<(128 * 7 + 255) / 256, 256>>>(fw1, fwm1, 128 * 7);
    midtap_split<<<(256 * 128 + 255) / 256, 256>>>(fw2, fwm2h, fwm2l, 256 * 128);
    midtap_split<<<(512 * 256 + 255) / 256, 256>>>(fw3, fwm3h, fwm3l, 512 * 256);
    split_plain<<<(512 * 512 + 255) / 256, 256>>>(Wda, Wdah, Wdal, 512 * 512);
    split_plain<<<(512 * 512 + 255) / 256, 256>>>(Wfa, Wfah, Wfal, 512 * 512);
    split_plain<<<(512 * 512 + 255) / 256, 256>>>(Watt, Watth, Wattl, 512 * 512);
    split_plain<<<(1024 * 1024 + 255) / 256, 256>>>(W1, W1h, W1l, 1024 * 1024);
    split_plain<<<(1024 * 1024 + 255) / 256, 256>>>(W2, W2h, W2l, 1024 * 1024);
    split_plain<<<(512 * 1024 + 255) / 256, 256>>>(W3, W3h, W3l, 512 * 1024);

    // ---- feature branch (fatt needed by fused att epilogue) ----
    feat1_k<<<(BATCH * 128) / 256, 256>>>(feature, fwm1, fb1, hf1h, hf1l);
    gemm2<1,1><<<dim3(2, BATCH / 256), 256, GSMEM>>>(hf1h, hf1l, fwm2h, fwm2l, fb2,
        nullptr, nullptr, hf2h, hf2l, 256, 128, BATCH, 0L, 128L, 1);
    gemm2<1,2><<<dim3(4, BATCH / 256), 256, GSMEM>>>(hf2h, hf2l, fwm3h, fwm3l, fb3,
        nullptr, fnnf, fnnh, fnnl, 512, 256, BATCH, 0L, 256L, 1);
    gemm2<0,0><<<dim3(4, BATCH / 256), 256, GSMEM>>>(fnnh, fnnl, Wfah, Wfal, bfa,
        nullptr, fattf, nullptr, nullptr, 512, 512, BATCH, 0L, 512L, 1);

    // ---- drug conv stack (implicit GEMM, relu) ----
    gemm2<1,1><<<dim3(1, (BATCH * L1O) / 256), 256, GSMEM>>>(xh, xl, w1rh, w1rl, db1,
        nullptr, nullptr, h1h, h1l, 128, 512, L1O, (long)LD * 128, 128L, 1);
    gemm2<1,1><<<dim3(2, (BATCH * L2O) / 256), 256, GSMEM>>>(h1h, h1l, w2rh, w2rl, db2,
        nullptr, nullptr, h2h, h2l, 256, 768, L2O, (long)L1O * 128, 128L, 1);
    gemm2<1,2><<<dim3(4, (BATCH * L3O) / 256), 256, GSMEM>>>(h2h, h2l, w3rh, w3rl, db3,
        nullptr, dcf, dch, dcl, 512, 2048, L3O, (long)L2O * 256, 256L, 1);

    // s = relu(dc @ Wda^T + bda + fatt[b]) fused
    gemm2<3,1><<<dim3(4, (BATCH * L3O) / 256), 256, GSMEM>>>(dch, dcl, Wdah, Wdal, bda,
        fattf, nullptr, atth, attl, 512, 512, BATCH * L3O, 0L, 512L, L3O);

    // A = s @ Watt^T + batt
    gemm2<0,0><<<dim3(4, (BATCH * L3O) / 256), 256, GSMEM>>>(atth, attl, Watth, Wattl, batt,
        nullptr, Amf, nullptr, nullptr, 512, 512, BATCH * L3O, 0L, 512L, 1);

    // fused gating + max/mean reductions -> pair (hi/lo)
    reduce_k<<<BATCH, 512>>>(dcf, Amf, fnnf, pairh, pairl);

    // FC head (leaky relu)
    gemm2<2,1><<<dim3(8, BATCH / 256), 256, GSMEM>>>(pairh, pairl, W1h, W1l, b1,
        nullptr, nullptr, fh1h, fh1l, 1024, 1024, BATCH, 0L, 1024L, 1);
    gemm2<2,1><<<dim3(8, BATCH / 256), 256, GSMEM>>>(fh1h, fh1l, W2h, W2l, b2,
        nullptr, nullptr, fh2h, fh2l, 1024, 1024, BATCH, 0L, 1024L, 1);
    gemm2<2,0><<<dim3(4, BATCH / 256), 256, GSMEM>>>(fh2h, fh2l, W3h, W3l, b3,
        nullptr, fh3f, nullptr, nullptr, 512, 1024, BATCH, 0L, 1024L, 1);

    final_k<<<BATCH, 128>>>(fh3f, Wo, bo, out);
}

// round 5
// speedup vs baseline: 1.6756x; 1.0089x over previous
#include <cuda_runtime.h>
#include <cuda_bf16.h>
#include <math.h>
#include <stdint.h>

// ---------------- problem constants ----------------
#define BATCH 2048
#define LD    100
#define DIM   128
#define L1O   97
#define L2O   92
#define L3O   85

typedef __nv_bfloat16 bf16;

// ---------------- scratch (device globals; allocation-free) ----------------
__device__ bf16 g_xh [BATCH * LD  * DIM];   __device__ bf16 g_xl [BATCH * LD  * DIM];
__device__ bf16 g_h1h[BATCH * L1O * 128];   __device__ bf16 g_h1l[BATCH * L1O * 128];
__device__ bf16 g_h2h[BATCH * L2O * 256];   __device__ bf16 g_h2l[BATCH * L2O * 256];
__device__ bf16 g_dch[BATCH * L3O * 512];   __device__ bf16 g_dcl[BATCH * L3O * 512];
__device__ bf16 g_atth[BATCH * L3O * 512];  __device__ bf16 g_attl[BATCH * L3O * 512];
__device__ bf16 g_hf1h[BATCH * 128];        __device__ bf16 g_hf1l[BATCH * 128];
__device__ bf16 g_hf2h[BATCH * 256];        __device__ bf16 g_hf2l[BATCH * 256];
__device__ bf16 g_fnnh[BATCH * 512];        __device__ bf16 g_fnnl[BATCH * 512];
__device__ bf16 g_pairh[BATCH * 1024];      __device__ bf16 g_pairl[BATCH * 1024];
__device__ bf16 g_fh1h[BATCH * 1024];       __device__ bf16 g_fh1l[BATCH * 1024];
__device__ bf16 g_fh2h[BATCH * 1024];       __device__ bf16 g_fh2l[BATCH * 1024];
__device__ float g_Amf[BATCH * L3O * 512];
__device__ float g_fattf[BATCH * 512];
__device__ float g_fh3f[BATCH * 512];
__device__ float g_fwm1[128 * 7];
__device__ bf16 g_w1rh[128 * 512];   __device__ bf16 g_w1rl[128 * 512];
__device__ bf16 g_w2rh[256 * 768];   __device__ bf16 g_w2rl[256 * 768];
__device__ bf16 g_w3rh[512 * 2048];  __device__ bf16 g_w3rl[512 * 2048];
__device__ bf16 g_fwm2h[256 * 128];  __device__ bf16 g_fwm2l[256 * 128];
__device__ bf16 g_fwm3h[512 * 256];  __device__ bf16 g_fwm3l[512 * 256];
__device__ bf16 g_Wdah[512 * 512];   __device__ bf16 g_Wdal[512 * 512];
__device__ bf16 g_Wfah[512 * 512];   __device__ bf16 g_Wfal[512 * 512];
__device__ bf16 g_Watth[512 * 512];  __device__ bf16 g_Wattl[512 * 512];
__device__ bf16 g_W1h[1024 * 1024];  __device__ bf16 g_W1l[1024 * 1024];
__device__ bf16 g_W2h[1024 * 1024];  __device__ bf16 g_W2l[1024 * 1024];
__device__ bf16 g_W3h[512 * 1024];   __device__ bf16 g_W3l[512 * 1024];

// ---------------- helpers ----------------
__device__ __forceinline__ uint32_t smem_u32(const void* p) {
    uint32_t a;
    asm("{ .reg .u64 t; cvta.to.shared.u64 t, %1; cvt.u32.u64 %0, t; }"
        : "=r"(a) : "l"(p));
    return a;
}
__device__ __forceinline__ void ldm4(uint32_t* r, uint32_t saddr) {
    asm volatile("ldmatrix.sync.aligned.m8n8.x4.shared.b16 {%0,%1,%2,%3}, [%4];"
        : "=r"(r[0]), "=r"(r[1]), "=r"(r[2]), "=r"(r[3]) : "r"(saddr));
}
__device__ __forceinline__ void mma16816(float* d, const uint32_t* a,
                                         uint32_t b0, uint32_t b1) {
    asm volatile(
        "mma.sync.aligned.m16n8k16.row.col.f32.bf16.bf16.f32 "
        "{%0,%1,%2,%3}, {%4,%5,%6,%7}, {%8,%9}, {%0,%1,%2,%3};"
        : "+f"(d[0]), "+f"(d[1]), "+f"(d[2]), "+f"(d[3])
        : "r"(a[0]), "r"(a[1]), "r"(a[2]), "r"(a[3]), "r"(b0), "r"(b1));
}
#define CPA16(dst, src) \
    asm volatile("cp.async.cg.shared.global [%0], [%1], 16;" :: "r"(dst), "l"(src) : "memory")
#define CPCOMMIT() asm volatile("cp.async.commit_group;" ::: "memory")
template <int NW> __device__ __forceinline__ void cpwait() {
    asm volatile("cp.async.wait_group %0;" :: "n"(NW) : "memory");
}
__device__ __forceinline__ uint32_t pack2(float x, float y) {
    bf16 a = __float2bfloat16(x), b = __float2bfloat16(y);
    return (uint32_t)__bfloat16_as_ushort(a) | ((uint32_t)__bfloat16_as_ushort(b) << 16);
}
__device__ __forceinline__ float bf16lo_res(float x) {
    return x - __bfloat162float(__float2bfloat16(x));
}
__device__ __forceinline__ void split1(float v, bf16& h, bf16& l) {
    h = __float2bfloat16(v);
    l = __float2bfloat16(v - __bfloat162float(h));
}

// ---------------- GEMM: C = act(Ahl * Whl^T + bias [+ extra]) ----------------
// CTA 256x128, 8 warps (4x2), warp 64x64. K staged 32 via cp.async, 2 stages.
// 3 separated MMA passes per k16 (hi*hi, lo*hi, hi*lo) — no acc RAW back-to-back.
#define ROWB   80u
#define AREG   20480u
#define BREG   10240u
#define STG    61440u
#define GSMEM  (2 * 61440)

template <int ACT, int OM>  // ACT: 0 none,1 relu,2 leaky,3 relu(bias+extra); OM: 0 f32,1 hilo
__global__ __launch_bounds__(256, 1)
void gemm2(const bf16* __restrict__ Ah, const bf16* __restrict__ Al,
           const bf16* __restrict__ Wh, const bf16* __restrict__ Wl,
           const float* __restrict__ bias, const float* __restrict__ extra,
           float* __restrict__ Cf, bf16* __restrict__ Ch, bf16* __restrict__ Cl,
           int N, int K, int Lout, long sOuter, long sInner, int rowdiv) {
    extern __shared__ char sm[];
    const uint32_t smb = smem_u32(sm);
    const int tid = threadIdx.x;
    const int wid = tid >> 5, lane = tid & 31;
    const int m0 = blockIdx.y * 256, n0 = blockIdx.x * 128;
    const int wm = wid >> 1, wn = wid & 1;

    const int mrow = m0 + tid;
    const long aoff = (long)(mrow / Lout) * sOuter + (long)(mrow % Lout) * sInner;
    const bf16* aH = Ah + aoff;
    const bf16* aL = Al + aoff;
    const int brow = n0 + (tid >> 1);
    const bf16* bH = Wh + (long)brow * K;
    const bf16* bL = Wl + (long)brow * K;
    const int bseg = (tid & 1) * 2;

    const uint32_t aDst = smb + (uint32_t)tid * ROWB;
    const uint32_t bDst = smb + 2u * AREG + (uint32_t)(tid >> 1) * ROWB + (uint32_t)bseg * 16u;

    const int laneR = lane & 15;
    const uint32_t laneC = (uint32_t)(lane >> 4) * 16u;
    const uint32_t aBase = smb + (uint32_t)(wm * 64 + laneR) * ROWB + laneC;
    const uint32_t bBase = smb + 2u * AREG + (uint32_t)(wn * 64 + laneR) * ROWB + laneC;

    float acc[4][8][4];
#pragma unroll
    for (int i = 0; i < 4; i++)
#pragma unroll
        for (int j = 0; j < 8; j++)
#pragma unroll
            for (int k = 0; k < 4; k++) acc[i][j][k] = 0.f;

    const int T = K / 32;

    {
        const uint32_t sb = 0;
#pragma unroll
        for (int s = 0; s < 4; s++) CPA16(aDst + sb + s * 16u, aH + s * 8);
#pragma unroll
        for (int s = 0; s < 4; s++) CPA16(aDst + sb + AREG + s * 16u, aL + s * 8);
#pragma unroll
        for (int s = 0; s < 2; s++) CPA16(bDst + sb + s * 16u, bH + (bseg + s) * 8);
#pragma unroll
        for (int s = 0; s < 2; s++) CPA16(bDst + sb + BREG + s * 16u, bL + (bseg + s) * 8);
        CPCOMMIT();
    }

    for (int t = 0; t < T; ++t) {
        if (t + 1 < T) {
            const int k0 = (t + 1) * 32;
            const uint32_t sb = (uint32_t)((t + 1) & 1) * STG;
#pragma unroll
            for (int s = 0; s < 4; s++) CPA16(aDst + sb + s * 16u, aH + k0 + s * 8);
#pragma unroll
            for (int s = 0; s < 4; s++) CPA16(aDst + sb + AREG + s * 16u, aL + k0 + s * 8);
#pragma unroll
            for (int s = 0; s < 2; s++) CPA16(bDst + sb + s * 16u, bH + k0 + (bseg + s) * 8);
#pragma unroll
            for (int s = 0; s < 2; s++) CPA16(bDst + sb + BREG + s * 16u, bL + k0 + (bseg + s) * 8);
            CPCOMMIT();
            cpwait<1>();
        } else {
            cpwait<0>();
        }
        __syncthreads();

        const uint32_t soff = (uint32_t)(t & 1) * STG;
#pragma unroll
        for (int j = 0; j < 2; j++) {
            const uint32_t ja = soff + (uint32_t)j * 32u;
            uint32_t ah[4][4], al[4][4], bh[4][4], bl[4][4];
#pragma unroll
            for (int mt = 0; mt < 4; mt++) {
                ldm4(ah[mt], aBase + ja + (uint32_t)mt * (16u * ROWB));
                ldm4(al[mt], aBase + ja + (uint32_t)mt * (16u * ROWB) + AREG);
            }
#pragma unroll
            for (int nt = 0; nt < 4; nt++) {
                ldm4(bh[nt], bBase + ja + (uint32_t)nt * (16u * ROWB));
                ldm4(bl[nt], bBase + ja + (uint32_t)nt * (16u * ROWB) + BREG);
            }
            // pass 1: hi*hi  (each acc touched once)
#pragma unroll
            for (int nt = 0; nt < 4; nt++)
#pragma unroll
                for (int mt = 0; mt < 4; mt++) {
                    mma16816(acc[mt][2 * nt],     ah[mt], bh[nt][0], bh[nt][2]);
                    mma16816(acc[mt][2 * nt + 1], ah[mt], bh[nt][1], bh[nt][3]);
                }
            // pass 2: lo*hi
#pragma unroll
            for (int nt = 0; nt < 4; nt++)
#pragma unroll
                for (int mt = 0; mt < 4; mt++) {
                    mma16816(acc[mt][2 * nt],     al[mt], bh[nt][0], bh[nt][2]);
                    mma16816(acc[mt][2 * nt + 1], al[mt], bh[nt][1], bh[nt][3]);
                }
            // pass 3: hi*lo
#pragma unroll
            for (int nt = 0; nt < 4; nt++)
#pragma unroll
                for (int mt = 0; mt < 4; mt++) {
                    mma16816(acc[mt][2 * nt],     ah[mt], bl[nt][0], bl[nt][2]);
                    mma16816(acc[mt][2 * nt + 1], ah[mt], bl[nt][1], bl[nt][3]);
                }
        }
        __syncthreads();
    }

    // ---- epilogue ----
    const int lr2 = lane >> 2;
    const int lc2 = (lane & 3) * 2;
#pragma unroll
    for (int mt = 0; mt < 4; mt++) {
#pragma unroll
        for (int h = 0; h < 2; h++) {
            const long m = (long)m0 + wm * 64 + mt * 16 + h * 8 + lr2;
            const long rowb = m * (long)N;
            const float* erow = (ACT == 3) ? (extra + (long)(m / rowdiv) * N) : nullptr;
#pragma unroll
            for (int nt2 = 0; nt2 < 8; nt2++) {
                const int n = n0 + wn * 64 + nt2 * 8 + lc2;
                float vx = acc[mt][nt2][2 * h]     + bias[n];
                float vy = acc[mt][nt2][2 * h + 1] + bias[n + 1];
                if (ACT == 3) { vx += erow[n]; vy += erow[n + 1]; }
                if (ACT == 1 || ACT == 3) {
                    vx = fmaxf(vx, 0.f); vy = fmaxf(vy, 0.f);
                } else if (ACT == 2) {
                    vx = vx > 0.f ? vx : 0.01f * vx;
                    vy = vy > 0.f ? vy : 0.01f * vy;
                }
                if (OM == 0)
                    *(float2*)(Cf + rowb + n) = make_float2(vx, vy);
                else {
                    *(uint32_t*)(Ch + rowb + n) = pack2(vx, vy);
                    *(uint32_t*)(Cl + rowb + n) = pack2(bf16lo_res(vx), bf16lo_res(vy));
                }
            }
        }
    }
}

// ---------------- prep / glue kernels ----------------
__global__ void embed_split(const int* __restrict__ drug, const float* __restrict__ emb,
                            bf16* __restrict__ xh, bf16* __restrict__ xl) {
    int idx = blockIdx.x * blockDim.x + threadIdx.x;
    const int total = BATCH * LD * (DIM / 4);
    if (idx >= total) return;
    int d4 = idx & 31;
    int bl = idx >> 5;
    int tok = drug[bl];
    float4 v = ((const float4*)emb)[(size_t)tok * 32 + d4];
    size_t pos = (size_t)bl * 128 + d4 * 4;
    *(uint2*)(xh + pos) = make_uint2(pack2(v.x, v.y), pack2(v.z, v.w));
    *(uint2*)(xl + pos) = make_uint2(pack2(bf16lo_res(v.x), bf16lo_res(v.y)),
                                     pack2(bf16lo_res(v.z), bf16lo_res(v.w)));
}

__global__ void reorder_w_split(const float* __restrict__ w, bf16* __restrict__ wh,
                                bf16* __restrict__ wl, int O, int Ci, int Kw) {
    int idx = blockIdx.x * blockDim.x + threadIdx.x;
    int total = O * Ci * Kw;
    if (idx >= total) return;
    int o = idx / (Ci * Kw);
    int rr = idx - o * (Ci * Kw);
    int i = rr / Kw;
    int k = rr - i * Kw;
    size_t t = (size_t)o * Ci * Kw + k * Ci + i;
    split1(w[idx], wh[t], wl[t]);
}

__global__ void midtap_split(const float* __restrict__ w, bf16* __restrict__ wh,
                             bf16* __restrict__ wl, int total) {
    int idx = blockIdx.x * blockDim.x + threadIdx.x;
    if (idx >= total) return;
    split1(w[idx * 3 + 1], wh[idx], wl[idx]);
}

__global__ void midtap_f32(const float* __restrict__ w, float* __restrict__ wr, int total) {
    int idx = blockIdx.x * blockDim.x + threadIdx.x;
    if (idx >= total) return;
    wr[idx] = w[idx * 3 + 1];
}

__global__ void split_plain(const float* __restrict__ w, bf16* __restrict__ wh,
                            bf16* __restrict__ wl, int total) {
    int idx = blockIdx.x * blockDim.x + threadIdx.x;
    if (idx >= total) return;
    split1(w[idx], wh[idx], wl[idx]);
}

__global__ void feat1_k(const float* __restrict__ feat, const float* __restrict__ wm,
                        const float* __restrict__ bias,
                        bf16* __restrict__ oh, bf16* __restrict__ ol) {
    int idx = blockIdx.x * blockDim.x + threadIdx.x;
    if (idx >= BATCH * 128) return;
    int b = idx >> 7, o = idx & 127;
    float s = bias[o];
#pragma unroll
    for (int i = 0; i < 7; i++) s = fmaf(feat[b * 7 + i], wm[o * 7 + i], s);
    s = fmaxf(s, 0.f);
    split1(s, oh[idx], ol[idx]);
}

// reduce reads dc (hi+lo), Am (f32), fnn (hi+lo)
__global__ void reduce_k(const bf16* __restrict__ dch, const bf16* __restrict__ dcl,
                         const float* __restrict__ Am,
                         const bf16* __restrict__ fnnh, const bf16* __restrict__ fnnl,
                         bf16* __restrict__ ph, bf16* __restrict__ pl) {
    int b = blockIdx.x;
    int c = threadIdx.x;
    const size_t base = (size_t)b * L3O * 512 + c;
    float mx = -1e30f, smv = 0.f;
#pragma unroll 5
    for (int l = 0; l < L3O; l++) {
        float a = Am[base + (size_t)l * 512];
        float d = __bfloat162float(dch[base + (size_t)l * 512])
                + __bfloat162float(dcl[base + (size_t)l * 512]);
        float sg = 1.f / (1.f + expf(-a));
        mx = fmaxf(mx, d * (0.5f + sg));
        smv += a;
    }
    float fsig = 1.f / (1.f + expf(-smv * (1.0f / L3O)));
    float vf = (__bfloat162float(fnnh[(size_t)b * 512 + c])
              + __bfloat162float(fnnl[(size_t)b * 512 + c])) * (0.5f + fsig);
    split1(mx, ph[(size_t)b * 1024 + c],       pl[(size_t)b * 1024 + c]);
    split1(vf, ph[(size_t)b * 1024 + 512 + c], pl[(size_t)b * 1024 + 512 + c]);
}

__global__ void final_k(const float* __restrict__ h3, const float* __restrict__ Wo,
                        const float* __restrict__ bo, float* __restrict__ out) {
    int b = blockIdx.x;
    int t = threadIdx.x;
    float s = 0.f;
#pragma unroll
    for (int c = t; c < 512; c += 128) s = fmaf(h3[(size_t)b * 512 + c], Wo[c], s);
#pragma unroll
    for (int o = 16; o > 0; o >>= 1) s += __shfl_down_sync(0xffffffffu, s, o);
    __shared__ float red[4];
    if ((t & 31) == 0) red[t >> 5] = s;
    __syncthreads();
    if (t == 0) out[b] = red[0] + red[1] + red[2] + red[3] + bo[0];
}

// ---------------- host launch ----------------
#define GADDR(p, sym) cudaGetSymbolAddress((void**)&p, sym)

extern "C" void kernel_launch(void* const* d_in, const int* in_sizes, int n_in,
                              void* d_out, int out_size) {
    const int*   drug    = (const int*)  d_in[0];
    const float* feature = (const float*)d_in[1];
    const float* emb     = (const float*)d_in[2];
    const float* dw1 = (const float*)d_in[3];  const float* db1 = (const float*)d_in[4];
    const float* dw2 = (const float*)d_in[5];  const float* db2 = (const float*)d_in[6];
    const float* dw3 = (const float*)d_in[7];  const float* db3 = (const float*)d_in[8];
    const float* fw1 = (const float*)d_in[9];  const float* fb1 = (const float*)d_in[10];
    const float* fw2 = (const float*)d_in[11]; const float* fb2 = (const float*)d_in[12];
    const float* fw3 = (const float*)d_in[13]; const float* fb3 = (const float*)d_in[14];
    const float* Wda = (const float*)d_in[15]; const float* bda = (const float*)d_in[16];
    const float* Wfa = (const float*)d_in[17]; const float* bfa = (const float*)d_in[18];
    const float* Watt= (const float*)d_in[19]; const float* batt= (const float*)d_in[20];
    const float* W1  = (const float*)d_in[21]; const float* b1  = (const float*)d_in[22];
    const float* W2  = (const float*)d_in[23]; const float* b2  = (const float*)d_in[24];
    const float* W3  = (const float*)d_in[25]; const float* b3  = (const float*)d_in[26];
    const float* Wo  = (const float*)d_in[27]; const float* bo  = (const float*)d_in[28];
    float* out = (float*)d_out;

    bf16 *xh,*xl,*h1h,*h1l,*h2h,*h2l,*dch,*dcl,*atth,*attl;
    bf16 *hf1h,*hf1l,*hf2h,*hf2l,*fnnh,*fnnl,*pairh,*pairl,*fh1h,*fh1l,*fh2h,*fh2l;
    bf16 *w1rh,*w1rl,*w2rh,*w2rl,*w3rh,*w3rl,*fwm2h,*fwm2l,*fwm3h,*fwm3l;
    bf16 *Wdah,*Wdal,*Wfah,*Wfal,*Watth,*Wattl,*W1h,*W1l,*W2h,*W2l,*W3h,*W3l;
    float *Amf,*fattf,*fh3f,*fwm1;
    GADDR(xh, g_xh); GADDR(xl, g_xl);
    GADDR(h1h, g_h1h); GADDR(h1l, g_h1l);
    GADDR(h2h, g_h2h); GADDR(h2l, g_h2l);
    GADDR(dch, g_dch); GADDR(dcl, g_dcl);
    GADDR(atth, g_atth); GADDR(attl, g_attl);
    GADDR(hf1h, g_hf1h); GADDR(hf1l, g_hf1l);
    GADDR(hf2h, g_hf2h); GADDR(hf2l, g_hf2l);
    GADDR(fnnh, g_fnnh); GADDR(fnnl, g_fnnl);
    GADDR(pairh, g_pairh); GADDR(pairl, g_pairl);
    GADDR(fh1h, g_fh1h); GADDR(fh1l, g_fh1l);
    GADDR(fh2h, g_fh2h); GADDR(fh2l, g_fh2l);
    GADDR(w1rh, g_w1rh); GADDR(w1rl, g_w1rl);
    GADDR(w2rh, g_w2rh); GADDR(w2rl, g_w2rl);
    GADDR(w3rh, g_w3rh); GADDR(w3rl, g_w3rl);
    GADDR(fwm2h, g_fwm2h); GADDR(fwm2l, g_fwm2l);
    GADDR(fwm3h, g_fwm3h); GADDR(fwm3l, g_fwm3l);
    GADDR(Wdah, g_Wdah); GADDR(Wdal, g_Wdal);
    GADDR(Wfah, g_Wfah); GADDR(Wfal, g_Wfal);
    GADDR(Watth, g_Watth); GADDR(Wattl, g_Wattl);
    GADDR(W1h, g_W1h); GADDR(W1l, g_W1l);
    GADDR(W2h, g_W2h); GADDR(W2l, g_W2l);
    GADDR(W3h, g_W3h); GADDR(W3l, g_W3l);
    GADDR(Amf, g_Amf); GADDR(fattf, g_fattf);
    GADDR(fh3f, g_fh3f); GADDR(fwm1, g_fwm1);

    cudaFuncSetAttribute(gemm2<0,0>, cudaFuncAttributeMaxDynamicSharedMemorySize, GSMEM);
    cudaFuncSetAttribute(gemm2<1,1>, cudaFuncAttributeMaxDynamicSharedMemorySize, GSMEM);
    cudaFuncSetAttribute(gemm2<3,1>, cudaFuncAttributeMaxDynamicSharedMemorySize, GSMEM);
    cudaFuncSetAttribute(gemm2<2,1>, cudaFuncAttributeMaxDynamicSharedMemorySize, GSMEM);
    cudaFuncSetAttribute(gemm2<2,0>, cudaFuncAttributeMaxDynamicSharedMemorySize, GSMEM);

    // ---- prep for drug conv stack, then convs early (ncu -s 5 lands on conv GEMM) ----
    embed_split<<<(BATCH * LD * 32 + 255) / 256, 256>>>(drug, emb, xh, xl);          // 0
    reorder_w_split<<<(128 * 128 * 4 + 255) / 256, 256>>>(dw1, w1rh, w1rl, 128, 128, 4); // 1
    reorder_w_split<<<(256 * 128 * 6 + 255) / 256, 256>>>(dw2, w2rh, w2rl, 256, 128, 6); // 2
    reorder_w_split<<<(512 * 256 * 8 + 255) / 256, 256>>>(dw3, w3rh, w3rl, 512, 256, 8); // 3

    gemm2<1,1><<<dim3(1, (BATCH * L1O) / 256), 256, GSMEM>>>(xh, xl, w1rh, w1rl, db1,    // 4
        nullptr, nullptr, h1h, h1l, 128, 512, L1O, (long)LD * 128, 128L, 1);
    gemm2<1,1><<<dim3(2, (BATCH * L2O) / 256), 256, GSMEM>>>(h1h, h1l, w2rh, w2rl, db2,  // 5
        nullptr, nullptr, h2h, h2l, 256, 768, L2O, (long)L1O * 128, 128L, 1);
    gemm2<1,1><<<dim3(4, (BATCH * L3O) / 256), 256, GSMEM>>>(h2h, h2l, w3rh, w3rl, db3,  // 6
        nullptr, nullptr, dch, dcl, 512, 2048, L3O, (long)L2O * 256, 256L, 1);

    // ---- feature branch ----
    midtap_f32  <<<(128 * 7 + 255) / 256, 256>>>(fw1, fwm1, 128 * 7);
    midtap_split<<<(256 * 128 + 255) / 256, 256>>>(fw2, fwm2h, fwm2l, 256 * 128);
    midtap_split<<<(512 * 256 + 255) / 256, 256>>>(fw3, fwm3h, fwm3l, 512 * 256);
    split_plain<<<(512 * 512 + 255) / 256, 256>>>(Wda, Wdah, Wdal, 512 * 512);
    split_plain<<<(512 * 512 + 255) / 256, 256>>>(Wfa, Wfah, Wfal, 512 * 512);
    split_plain<<<(512 * 512 + 255) / 256, 256>>>(Watt, Watth, Wattl, 512 * 512);

    feat1_k<<<(BATCH * 128) / 256, 256>>>(feature, fwm1, fb1, hf1h, hf1l);
    gemm2<1,1><<<dim3(2, BATCH / 256), 256, GSMEM>>>(hf1h, hf1l, fwm2h, fwm2l, fb2,
        nullptr, nullptr, hf2h, hf2l, 256, 128, BATCH, 0L, 128L, 1);
    gemm2<1,1><<<dim3(4, BATCH / 256), 256, GSMEM>>>(hf2h, hf2l, fwm3h, fwm3l, fb3,
        nullptr, nullptr, fnnh, fnnl, 512, 256, BATCH, 0L, 256L, 1);
    gemm2<0,0><<<dim3(4, BATCH / 256), 256, GSMEM>>>(fnnh, fnnl, Wfah, Wfal, bfa,
        nullptr, fattf, nullptr, nullptr, 512, 512, BATCH, 0L, 512L, 1);

    // s = relu(dc @ Wda^T + bda + fatt[b]) fused
    gemm2<3,1><<<dim3(4, (BATCH * L3O) / 256), 256, GSMEM>>>(dch, dcl, Wdah, Wdal, bda,
        fattf, nullptr, atth, attl, 512, 512, BATCH * L3O, 0L, 512L, L3O);

    // A = s @ Watt^T + batt
    gemm2<0,0><<<dim3(4, (BATCH * L3O) / 256), 256, GSMEM>>>(atth, attl, Watth, Wattl, batt,
        nullptr, Amf, nullptr, nullptr, 512, 512, BATCH * L3O, 0L, 512L, 1);

    // fused gating + max/mean reductions -> pair (hi/lo)
    reduce_k<<<BATCH, 512>>>(dch, dcl, Amf, fnnh, fnnl, pairh, pairl);

    // FC head weights + GEMMs (leaky relu)
    split_plain<<<(1024 * 1024 + 255) / 256, 256>>>(W1, W1h, W1l, 1024 * 1024);
    split_plain<<<(1024 * 1024 + 255) / 256, 256>>>(W2, W2h, W2l, 1024 * 1024);
    split_plain<<<(512 * 1024 + 255) / 256, 256>>>(W3, W3h, W3l, 512 * 1024);

    gemm2<2,1><<<dim3(8, BATCH / 256), 256, GSMEM>>>(pairh, pairl, W1h, W1l, b1,
        nullptr, nullptr, fh1h, fh1l, 1024, 1024, BATCH, 0L, 1024L, 1);
    gemm2<2,1><<<dim3(8, BATCH / 256), 256, GSMEM>>>(fh1h, fh1l, W2h, W2l, b2,
        nullptr, nullptr, fh2h, fh2l, 1024, 1024, BATCH, 0L, 1024L, 1);
    gemm2<2,0><<<dim3(4, BATCH / 256), 256, GSMEM>>>(fh2h, fh2l, W3h, W3l, b3,
        nullptr, fh3f, nullptr, nullptr, 512, 1024, BATCH, 0L, 1024L, 1);

    final_k<<<BATCH, 128>>>(fh3f, Wo, bo, out);
}